// round 16
// baseline (speedup 1.0000x reference)
#include <cuda_runtime.h>
#include <cstdint>

#define NF 255
#define NH 128
#define NC 16
#define NIMG 64
#define PI2 6.28318530717958647692f

__device__ __forceinline__ uint32_t f2tf(float x){
    uint32_t r; asm("cvt.rna.tf32.f32 %0, %1;" : "=r"(r) : "f"(x)); return r;
}
__device__ __forceinline__ float2 spl(float x){
    uint32_t h = f2tf(x);
    float hf = __uint_as_float(h);
    uint32_t l = f2tf(x - hf);
    return make_float2(hf, __uint_as_float(l));
}
__device__ __forceinline__ float4 spl2(float re, float im){
    float2 a=spl(re), b=spl(im);
    return make_float4(a.x,a.y,b.x,b.y);
}
__device__ __forceinline__ void mmaT(float* c, const uint32_t* a, const uint32_t* b){
    asm("mma.sync.aligned.m16n8k8.row.col.f32.tf32.tf32.f32 "
        "{%0,%1,%2,%3},{%4,%5,%6,%7},{%8,%9},{%0,%1,%2,%3};"
        : "+f"(c[0]),"+f"(c[1]),"+f"(c[2]),"+f"(c[3])
        : "r"(a[0]),"r"(a[1]),"r"(a[2]),"r"(a[3]),"r"(b[0]),"r"(b[1]));
}
__device__ __forceinline__ void mma3(float* c, const uint32_t* ah, const uint32_t* al,
                                     const uint32_t* bh, const uint32_t* bl){
    mmaT(c, ah, bh); mmaT(c, ah, bl); mmaT(c, al, bh);
}
// A fragment (m16 x k8) from (hi,lo) float2 plane, pitch 20 float2
__device__ __forceinline__ void ldA(uint32_t* h, uint32_t* l, const float2* P, int m, int k){
    float2 v0=P[m*20+k],     v1=P[(m+8)*20+k];
    float2 v2=P[m*20+k+4],   v3=P[(m+8)*20+k+4];
    h[0]=__float_as_uint(v0.x); l[0]=__float_as_uint(v0.y);
    h[1]=__float_as_uint(v1.x); l[1]=__float_as_uint(v1.y);
    h[2]=__float_as_uint(v2.x); l[2]=__float_as_uint(v2.y);
    h[3]=__float_as_uint(v3.x); l[3]=__float_as_uint(v3.y);
}
__device__ __forceinline__ void ldB(uint32_t* h, uint32_t* l, const float2* P, int n, int k){
    float2 v0=P[n*20+k], v1=P[n*20+k+4];
    h[0]=__float_as_uint(v0.x); l[0]=__float_as_uint(v0.y);
    h[1]=__float_as_uint(v1.x); l[1]=__float_as_uint(v1.y);
}

// scratch (device globals: allocation-free rule) — pre-split (hi,lo) layouts
__device__ float4 g_Fq[NF*NH];          // F: (rh,rl,ih,il), F=(cos,-sin)[v*128+h]
__device__ float4 g_Gq[NH*NF];          // G: (cos,sin)[w'*255+v] pre-split
__device__ float4 g_Eq[NH*NH];          // E: (er, -ei) pre-split, er=cu*cos, ei=cu*sin
__device__ float2 g_xq[NIMG*NH*NH];     // x transposed, pre-split (hi,lo)
__device__ float4 g_A4[NIMG*NH*NH];     // stage1 out pre-split [img][u][w]
__device__ float4 g_Y4[NIMG*NH*NF];     // (Xf*Kh) pre-split [img][u][v]
__device__ float2 g_Kh[NC*NH*NF];       // folded kernel (plain)
__device__ float4 g_St4[NIMG*NH*NH];    // stage3 out pre-split TRANSPOSED [img][w'][u]

__global__ void k_twiddles(){
    int i = blockIdx.x*blockDim.x + threadIdx.x;
    const float w0 = PI2/255.0f;
    if(i < NF*NH){
        int v=i/NH, h=i%NH; float a=w0*(float)((v*h)%NF);
        g_Fq[i]=spl2(cosf(a), -sinf(a)); return;
    }
    int j=i-NF*NH;
    if(j < NH*NF){
        int wq=j/NF, v=j%NF; float a=w0*(float)((v*(wq+63))%NF);
        g_Gq[j]=spl2(cosf(a), sinf(a)); return;
    }
    int e=j-NH*NF;
    if(e < NH*NH){
        int h=e/NH, u=e%NH; float a=w0*(float)((u*(h+63))%NF);
        float cu = u?2.f:1.f;
        g_Eq[e]=spl2(cu*cosf(a), -cu*sinf(a));
    }
}

// in[b][h][w][c] -> g_xq[(b*16+c)][w][h] pre-split, smem-staged
__global__ void k_transpose(const float* __restrict__ in){
    __shared__ float ts[NC*16*36];
    const int b=blockIdx.z, h0=blockIdx.y*32, w0=blockIdx.x*16, tid=threadIdx.x;
#pragma unroll
    for(int it=0;it<2;it++){
        int p=tid+it*256, h=p>>4, w=p&15;
        const float4* src=(const float4*)(in+(size_t)((b*NH+h0+h)*NH+w0+w)*NC);
#pragma unroll
        for(int q=0;q<4;q++){
            float4 v=src[q]; int cb=q*4;
            ts[(cb+0)*576+w*36+h]=v.x; ts[(cb+1)*576+w*36+h]=v.y;
            ts[(cb+2)*576+w*36+h]=v.z; ts[(cb+3)*576+w*36+h]=v.w;
        }
    }
    __syncthreads();
    int h4=(tid&7)*4;
#pragma unroll
    for(int it=0;it<8;it++){
        int q=(tid>>3)+it*32, c=q>>4, w=q&15;
        float4 v=*(const float4*)&ts[c*576+w*36+h4];
        size_t base=(size_t)((b*NC+c)*NH+(w0+w))*NH + h0 + h4;
        float2 s0=spl(v.x), s1=spl(v.y), s2=spl(v.z), s3=spl(v.w);
        *(float4*)&g_xq[base]   = make_float4(s0.x,s0.y,s1.x,s1.y);
        *(float4*)&g_xq[base+2] = make_float4(s2.x,s2.y,s3.x,s3.y);
    }
}

// fused Keff (sum over cout) + Hermitian fold + 1/255^2 scale
__global__ void k_keffkh(const float* __restrict__ kr, const float* __restrict__ ki){
    int idx = blockIdx.x*blockDim.x + threadIdx.x;
    if(idx >= NH*NF*NC) return;
    int c = idx&15, v = (idx>>4)%NF, u = idx/(16*NF);
    int u2=(NF-u)%NF, v2=(NF-v)%NF;
    size_t p1=((size_t)(u*NF+v)*NC+c)*16, p2=((size_t)(u2*NF+v2)*NC+c)*16;
    float sr1=0,si1=0,sr2=0,si2=0; const float4* a;
    a=(const float4*)(kr+p1);
#pragma unroll
    for(int j=0;j<4;j++){float4 t=a[j];sr1+=t.x+t.y+t.z+t.w;}
    a=(const float4*)(ki+p1);
#pragma unroll
    for(int j=0;j<4;j++){float4 t=a[j];si1+=t.x+t.y+t.z+t.w;}
    a=(const float4*)(kr+p2);
#pragma unroll
    for(int j=0;j<4;j++){float4 t=a[j];sr2+=t.x+t.y+t.z+t.w;}
    a=(const float4*)(ki+p2);
#pragma unroll
    for(int j=0;j<4;j++){float4 t=a[j];si2+=t.x+t.y+t.z+t.w;}
    const float s = 0.5f/65025.0f;
    g_Kh[(c*NH+u)*NF+v]=make_float2(s*(sr1+sr2), s*(si1-si2));
}

// ---------------------------------------------------------------------------
// Tensor GEMMs: CTA 64m x 64n, 128 thr (4 warps x m16 stripe, full n64).
// Fills are pure LDG+STS (operands pre-split). 3xTF32 mma m16n8k8.
// ---------------------------------------------------------------------------

// Stage1: A[img][u][w] = sum_h F[u][h]*x[img][w][h]  (cplx A, real B)
__global__ void __launch_bounds__(128) k_stage1(){
    __shared__ float2 AR[64*20], AI[64*20], BRp[64*20];
    const int img=blockIdx.z, n0=blockIdx.x*64, m0=blockIdx.y*64, tid=threadIdx.x;
    const int lane=tid&31, gl=lane>>2, cl=lane&3, mw=(tid>>5)*16;
    const int lk=tid&15, lr=tid>>4;
    const float2* Bg = g_xq + (size_t)img*NH*NH;
    float cR[8][4], cI[8][4];
#pragma unroll
    for(int i=0;i<8;i++)
#pragma unroll
        for(int j=0;j<4;j++){ cR[i][j]=0.f; cI[i][j]=0.f; }
    float4 pa[8]; float2 pb[8];
#pragma unroll
    for(int r=0;r<8;r++) pa[r]=g_Fq[(m0+lr+r*8)*NH+lk];
#pragma unroll
    for(int r=0;r<8;r++) pb[r]=Bg[(n0+lr+r*8)*NH+lk];
    for(int t=0;t<8;t++){
#pragma unroll
        for(int r=0;r<8;r++){ int m=lr+r*8;
            AR[m*20+lk]=make_float2(pa[r].x,pa[r].y);
            AI[m*20+lk]=make_float2(pa[r].z,pa[r].w);
            BRp[m*20+lk]=pb[r]; }
        __syncthreads();
        if(t<7){
            int k0=(t+1)*16;
#pragma unroll
            for(int r=0;r<8;r++) pa[r]=g_Fq[(m0+lr+r*8)*NH+k0+lk];
#pragma unroll
            for(int r=0;r<8;r++) pb[r]=Bg[(n0+lr+r*8)*NH+k0+lk];
        }
#pragma unroll
        for(int s=0;s<16;s+=8){
            uint32_t arh[4],arl[4],aih[4],ail[4];
            ldA(arh,arl,AR,mw+gl,s+cl);
            ldA(aih,ail,AI,mw+gl,s+cl);
#pragma unroll
            for(int nb=0;nb<8;nb++){
                uint32_t brh[2],brl[2];
                ldB(brh,brl,BRp,nb*8+gl,s+cl);
                mma3(cR[nb],arh,arl,brh,brl);
                mma3(cI[nb],aih,ail,brh,brl);
            }
        }
        __syncthreads();
    }
    float4* C = g_A4 + (size_t)img*NH*NH;
#pragma unroll
    for(int nb=0;nb<8;nb++){
        int n = n0+nb*8+2*cl, m = m0+mw+gl;
        C[m*NH+n]       = spl2(cR[nb][0],cI[nb][0]);
        C[m*NH+n+1]     = spl2(cR[nb][1],cI[nb][1]);
        C[(m+8)*NH+n]   = spl2(cR[nb][2],cI[nb][2]);
        C[(m+8)*NH+n+1] = spl2(cR[nb][3],cI[nb][3]);
    }
}

// Stage2: Xf = A*F (cplx x cplx); epilogue fuses *Kh and stores pre-split g_Y4
__global__ void __launch_bounds__(128) k_stage2(){
    __shared__ float2 AR[64*20], AI[64*20], BR[64*20], BI[64*20];
    const int img=blockIdx.z, n0=blockIdx.x*64, m0=blockIdx.y*64, tid=threadIdx.x;
    const int lane=tid&31, gl=lane>>2, cl=lane&3, mw=(tid>>5)*16;
    const int lk=tid&15, lr=tid>>4;
    const float4* Ag = g_A4 + (size_t)img*NH*NH;
    float cR[8][4], cI[8][4];
#pragma unroll
    for(int i=0;i<8;i++)
#pragma unroll
        for(int j=0;j<4;j++){ cR[i][j]=0.f; cI[i][j]=0.f; }
    float4 pa[8], pb[8];
#pragma unroll
    for(int r=0;r<8;r++) pa[r]=Ag[(m0+lr+r*8)*NH+lk];
#pragma unroll
    for(int r=0;r<8;r++){ int v=n0+lr+r*8;
        pb[r]=(v<NF)? g_Fq[v*NH+lk] : make_float4(0.f,0.f,0.f,0.f); }
    for(int t=0;t<8;t++){
#pragma unroll
        for(int r=0;r<8;r++){ int m=lr+r*8;
            AR[m*20+lk]=make_float2(pa[r].x,pa[r].y);
            AI[m*20+lk]=make_float2(pa[r].z,pa[r].w);
            BR[m*20+lk]=make_float2(pb[r].x,pb[r].y);
            BI[m*20+lk]=make_float2(pb[r].z,pb[r].w); }
        __syncthreads();
        if(t<7){
            int k0=(t+1)*16;
#pragma unroll
            for(int r=0;r<8;r++) pa[r]=Ag[(m0+lr+r*8)*NH+k0+lk];
#pragma unroll
            for(int r=0;r<8;r++){ int v=n0+lr+r*8;
                pb[r]=(v<NF)? g_Fq[v*NH+k0+lk] : make_float4(0.f,0.f,0.f,0.f); }
        }
#pragma unroll
        for(int s=0;s<16;s+=8){
            uint32_t arh[4],arl[4],aih[4],ail[4],anh[4],anl[4];
            ldA(arh,arl,AR,mw+gl,s+cl);
            ldA(aih,ail,AI,mw+gl,s+cl);
#pragma unroll
            for(int q=0;q<4;q++){ anh[q]=aih[q]^0x80000000u; anl[q]=ail[q]^0x80000000u; }
#pragma unroll
            for(int nb=0;nb<8;nb++){
                uint32_t brh[2],brl[2],bih[2],bil[2];
                ldB(brh,brl,BR,nb*8+gl,s+cl);
                ldB(bih,bil,BI,nb*8+gl,s+cl);
                mma3(cR[nb],arh,arl,brh,brl);   // + Ar*Br
                mma3(cR[nb],anh,anl,bih,bil);   // - Ai*Bi
                mma3(cI[nb],arh,arl,bih,bil);   // + Ar*Bi
                mma3(cI[nb],aih,ail,brh,brl);   // + Ai*Br
            }
        }
        __syncthreads();
    }
    const float2* Kg = g_Kh + (img&15)*NH*NF;
    float4* Y = g_Y4 + (size_t)img*NH*NF;
#pragma unroll
    for(int nb=0;nb<8;nb++){
        int n = n0+nb*8+2*cl, m = m0+mw+gl;
#pragma unroll
        for(int q=0;q<4;q++){
            int nn = n + (q&1), mm = m + (q>>1)*8;
            if(nn<NF){
                float xr=cR[nb][q], xi=cI[nb][q];
                float2 h=Kg[mm*NF+nn];
                Y[mm*NF+nn]=spl2(xr*h.x-xi*h.y, xr*h.y+xi*h.x);
            }
        }
    }
}

// Stage3: St[img][w'][u] = sum_v Y[u][v]*G[w'][v]  (A-fill = pure loads)
__global__ void __launch_bounds__(128) k_stage3(){
    __shared__ float2 AR[64*20], AI[64*20], BR[64*20], BI[64*20];
    const int img=blockIdx.z, n0=blockIdx.x*64, m0=blockIdx.y*64, tid=threadIdx.x;
    const int lane=tid&31, gl=lane>>2, cl=lane&3, mw=(tid>>5)*16;
    const int lk=tid&15, lr=tid>>4;
    const float4* Yg = g_Y4 + (size_t)img*NH*NF;
    float cR[8][4], cI[8][4];
#pragma unroll
    for(int i=0;i<8;i++)
#pragma unroll
        for(int j=0;j<4;j++){ cR[i][j]=0.f; cI[i][j]=0.f; }
    float4 pa[8], pb[8];
    {
        int kk=lk; bool ok=(kk<NF);
#pragma unroll
        for(int r=0;r<8;r++)
            pa[r]= ok ? Yg[(m0+lr+r*8)*NF+kk] : make_float4(0.f,0.f,0.f,0.f);
#pragma unroll
        for(int r=0;r<8;r++)
            pb[r]= ok ? g_Gq[(n0+lr+r*8)*NF+kk] : make_float4(0.f,0.f,0.f,0.f);
    }
    for(int t=0;t<16;t++){
#pragma unroll
        for(int r=0;r<8;r++){ int m=lr+r*8;
            AR[m*20+lk]=make_float2(pa[r].x,pa[r].y);
            AI[m*20+lk]=make_float2(pa[r].z,pa[r].w);
            BR[m*20+lk]=make_float2(pb[r].x,pb[r].y);
            BI[m*20+lk]=make_float2(pb[r].z,pb[r].w); }
        __syncthreads();
        if(t<15){
            int kk=(t+1)*16+lk; bool ok=(kk<NF);
#pragma unroll
            for(int r=0;r<8;r++)
                pa[r]= ok ? Yg[(m0+lr+r*8)*NF+kk] : make_float4(0.f,0.f,0.f,0.f);
#pragma unroll
            for(int r=0;r<8;r++)
                pb[r]= ok ? g_Gq[(n0+lr+r*8)*NF+kk] : make_float4(0.f,0.f,0.f,0.f);
        }
#pragma unroll
        for(int s=0;s<16;s+=8){
            uint32_t arh[4],arl[4],aih[4],ail[4],anh[4],anl[4];
            ldA(arh,arl,AR,mw+gl,s+cl);
            ldA(aih,ail,AI,mw+gl,s+cl);
#pragma unroll
            for(int q=0;q<4;q++){ anh[q]=aih[q]^0x80000000u; anl[q]=ail[q]^0x80000000u; }
#pragma unroll
            for(int nb=0;nb<8;nb++){
                uint32_t brh[2],brl[2],bih[2],bil[2];
                ldB(brh,brl,BR,nb*8+gl,s+cl);
                ldB(bih,bil,BI,nb*8+gl,s+cl);
                mma3(cR[nb],arh,arl,brh,brl);
                mma3(cR[nb],anh,anl,bih,bil);
                mma3(cI[nb],arh,arl,bih,bil);
                mma3(cI[nb],aih,ail,brh,brl);
            }
        }
        __syncthreads();
    }
    float4* C = g_St4 + (size_t)img*NH*NH;
#pragma unroll
    for(int nb=0;nb<8;nb++){            // store transposed pre-split: C[w'][u]
        int n = n0+nb*8+2*cl, m = m0+mw+gl;
        C[n*NH+m]       = spl2(cR[nb][0],cI[nb][0]);
        C[(n+1)*NH+m]   = spl2(cR[nb][1],cI[nb][1]);
        C[n*NH+m+8]     = spl2(cR[nb][2],cI[nb][2]);
        C[(n+1)*NH+m+8] = spl2(cR[nb][3],cI[nb][3]);
    }
}

// Stage4: out = bias + sum_u (Er*Sr - Ei*Si)
__global__ void __launch_bounds__(128) k_stage4(const float* __restrict__ bias,
                                               float* __restrict__ out){
    __shared__ float2 AE[64*20], AN[64*20], BR[64*20], BI[64*20];
    const int img=blockIdx.z, b2=img>>4, c=img&15;
    const int n0=blockIdx.x*64, m0=blockIdx.y*64, tid=threadIdx.x;
    const int lane=tid&31, gl=lane>>2, cl=lane&3, mw=(tid>>5)*16;
    const int lk=tid&15, lr=tid>>4;
    const float4* Sg = g_St4 + (size_t)img*NH*NH;
    float cO[8][4];
#pragma unroll
    for(int i=0;i<8;i++)
#pragma unroll
        for(int j=0;j<4;j++) cO[i][j]=0.f;
    float4 pe[8], ps[8];
#pragma unroll
    for(int r=0;r<8;r++) pe[r]=g_Eq[(m0+lr+r*8)*NH+lk];
#pragma unroll
    for(int r=0;r<8;r++) ps[r]=Sg[(n0+lr+r*8)*NH+lk];
    for(int t=0;t<8;t++){
#pragma unroll
        for(int r=0;r<8;r++){ int m=lr+r*8;
            AE[m*20+lk]=make_float2(pe[r].x,pe[r].y);
            AN[m*20+lk]=make_float2(pe[r].z,pe[r].w);
            BR[m*20+lk]=make_float2(ps[r].x,ps[r].y);
            BI[m*20+lk]=make_float2(ps[r].z,ps[r].w); }
        __syncthreads();
        if(t<7){
            int k0=(t+1)*16;
#pragma unroll
            for(int r=0;r<8;r++) pe[r]=g_Eq[(m0+lr+r*8)*NH+k0+lk];
#pragma unroll
            for(int r=0;r<8;r++) ps[r]=Sg[(n0+lr+r*8)*NH+k0+lk];
        }
#pragma unroll
        for(int s=0;s<16;s+=8){
            uint32_t aeh[4],ael[4],anh[4],anl[4];
            ldA(aeh,ael,AE,mw+gl,s+cl);
            ldA(anh,anl,AN,mw+gl,s+cl);
#pragma unroll
            for(int nb=0;nb<8;nb++){
                uint32_t brh[2],brl[2],bih[2],bil[2];
                ldB(brh,brl,BR,nb*8+gl,s+cl);
                ldB(bih,bil,BI,nb*8+gl,s+cl);
                mma3(cO[nb],aeh,ael,brh,brl);   // + er*Sr
                mma3(cO[nb],anh,anl,bih,bil);   // + (-ei)*Si
            }
        }
        __syncthreads();
    }
    float bv = bias[c];
#pragma unroll
    for(int nb=0;nb<8;nb++){
        int w = n0+nb*8+2*cl, h = m0+mw+gl;
        out[((size_t)((b2*NH+h)*NH+w  ))*NC+c] = cO[nb][0]+bv;
        out[((size_t)((b2*NH+h)*NH+w+1))*NC+c] = cO[nb][1]+bv;
        out[((size_t)((b2*NH+h+8)*NH+w  ))*NC+c] = cO[nb][2]+bv;
        out[((size_t)((b2*NH+h+8)*NH+w+1))*NC+c] = cO[nb][3]+bv;
    }
}

extern "C" void kernel_launch(void* const* d_in, const int* in_sizes, int n_in,
                              void* d_out, int out_size){
    const float* inp  = (const float*)d_in[0];
    const float* kr   = (const float*)d_in[1];
    const float* ki   = (const float*)d_in[2];
    const float* bias = (const float*)d_in[3];
    float* out = (float*)d_out;

    const int twN = NF*NH + NH*NF + NH*NH;
    k_twiddles<<<(twN+255)/256, 256>>>();
    dim3 tg(8,4,4);
    k_transpose<<<tg, 256>>>(inp);
    k_keffkh<<<(NH*NF*NC+255)/256, 256>>>(kr, ki);

    dim3 blk(128);
    dim3 g1(2,2,NIMG); k_stage1<<<g1, blk>>>();
    dim3 g2(4,2,NIMG); k_stage2<<<g2, blk>>>();
    dim3 g3(2,2,NIMG); k_stage3<<<g3, blk>>>();
    dim3 g4(2,2,NIMG); k_stage4<<<g4, blk>>>(bias, out);
}